// round 6
// baseline (speedup 1.0000x reference)
#include <cuda_runtime.h>
#include <cstdint>

// ---------------------------------------------------------------------------
// TractBundle: out = concat( x_a @ (Wa*Ma)^T, x_b @ (Wb*Mb)^T, x_c @ (Wc*Mc)^T )
// Masks: 64/64/32-sparse per row -> compressed sparse-gather.
// TOKS=32 (lane=token, scalar LDS): same crossbar efficiency as float2 but
// half the register pressure -> CHUNK=512 double-buffer + odd stride S=33
// (everything conflict-free) + one barrier per pass.
// ---------------------------------------------------------------------------

#define CHUNK 512                   // src elements staged per pass
#define S     33                    // smem row stride (odd -> conflict-free)
#define TOKS  32                    // tokens per block (1 per lane)
#define NDST  512                   // dst columns per block
#define DPW   16                    // dsts per warp
#define BUFW  (CHUNK * S)           // 16896 floats per buffer
#define SMEM_BYTES (2 * BUFW * 4)   // 135168

// Compressed tables: entry = ( (src&511)*33 , bits(w*m) ), 16B aligned rows
// for int4 paired loads. Splits transposed: spl[p * n_dst + dst].
__device__ __align__(16) int2 g_tabA[1024 * 64];
__device__ __align__(16) int2 g_tabB[512 * 64];
__device__ __align__(16) int2 g_tabC[512 * 32];
__device__ int g_splA[9 * 1024];
__device__ int g_splB[9 * 512];
__device__ int g_splC[5 * 512];

// ---------------------------------------------------------------------------
// prep_v2: one warp per dst row (2048 warp-rows). Ballot-free: lane loads its
// 16 strided mask values per 512-chunk (MLP=16), shfl inclusive scan for
// offsets, scattered writes. Entry order within a chunk is lane-major (sum
// order is irrelevant; only chunk membership matters).
// ---------------------------------------------------------------------------
__global__ void prep_all(const float* __restrict__ wa, const float* __restrict__ ma,
                         const float* __restrict__ wb, const float* __restrict__ mb,
                         const float* __restrict__ wc, const float* __restrict__ mc)
{
    int g    = (blockIdx.x * blockDim.x + threadIdx.x) >> 5;
    int lane = threadIdx.x & 31;

    const float *W, *M; int2* tab; int* spl;
    int src, n_dst, conn, row;
    if (g < 1024)      { W = wa; M = ma; tab = g_tabA; spl = g_splA;
                         src = 4096; n_dst = 1024; conn = 64; row = g; }
    else if (g < 1536) { W = wb; M = mb; tab = g_tabB; spl = g_splB;
                         src = 4096; n_dst = 512;  conn = 64; row = g - 1024; }
    else               { W = wc; M = mc; tab = g_tabC; spl = g_splC;
                         src = 2048; n_dst = 512;  conn = 32; row = g - 1536; }

    const float* wr = W + (size_t)row * src;
    const float* mr = M + (size_t)row * src;
    int2* trow = tab + (size_t)row * conn;

    if (lane == 0) spl[row] = 0;            // p = 0
    int total = 0;
    for (int c0 = 0; c0 < src; c0 += CHUNK) {
        float mv[16];
#pragma unroll
        for (int i = 0; i < 16; i++) mv[i] = mr[c0 + i * 32 + lane];
        int cnt = 0;
#pragma unroll
        for (int i = 0; i < 16; i++) cnt += (mv[i] != 0.0f);
        // inclusive scan over lanes
        int scan = cnt;
#pragma unroll
        for (int o = 1; o < 32; o <<= 1) {
            int v = __shfl_up_sync(0xffffffffu, scan, o);
            if (lane >= o) scan += v;
        }
        int chunk_total = __shfl_sync(0xffffffffu, scan, 31);
        int base = total + scan - cnt;      // exclusive prefix for this lane
        int k = 0;
#pragma unroll
        for (int i = 0; i < 16; i++) {
            if (mv[i] != 0.0f) {
                int s = c0 + i * 32 + lane;
                trow[base + k] = make_int2((s & (CHUNK - 1)) * S,
                                           __float_as_int(wr[s] * mv[i]));
                k++;
            }
        }
        total += chunk_total;
        if (lane == 0) spl[((c0 >> 9) + 1) * n_dst + row] = total;
    }
}

// ---------------------------------------------------------------------------
// Fused gather kernel, 1024 blocks x 1024 threads (32 warps).
//   [0,512)    tract A: tile = b>>1 (32-token tiles), dstblk = b&1
//   [512,768)  tract B;  [768,1024) tract C
// Staging: warp w = token (token0+w), lane = src position. Conflict-free STS.
// Gather:  warp-uniform dst (int4 paired table loads), lane = token. LDS.32
//          at q.x + lane: 32 consecutive words, conflict-free.
// Double buffer: stage chunk p+1 (regs, 8 at a time) during gather of p.
// One __syncthreads per pass.
// ---------------------------------------------------------------------------
__global__ __launch_bounds__(1024, 1)
void tract_fused(const float* __restrict__ xa,
                 const float* __restrict__ xb,
                 const float* __restrict__ xc,
                 float* __restrict__ out)
{
    extern __shared__ float xs[];
    const int tid  = threadIdx.x;
    const int lane = tid & 31;
    const int wid  = tid >> 5;

    // ---- block -> (tract, tile, dst block) dispatch ----
    const float* x; const int2* tab; const int* spl;
    int src, conn, passes, n_dst, col_off, token0, dst_base;
    int b = blockIdx.x;
    if (b < 512) {
        x = xa; tab = g_tabA; spl = g_splA;
        src = 4096; conn = 64; passes = 8; n_dst = 1024;
        col_off = 0; token0 = (b >> 1) * TOKS; dst_base = (b & 1) * NDST;
    } else if (b < 768) {
        x = xb; tab = g_tabB; spl = g_splB;
        src = 4096; conn = 64; passes = 8; n_dst = 512;
        col_off = 1024; token0 = (b - 512) * TOKS; dst_base = 0;
    } else {
        x = xc; tab = g_tabC; spl = g_splC;
        src = 2048; conn = 32; passes = 4; n_dst = 512;
        col_off = 1536; token0 = (b - 768) * TOKS; dst_base = 0;
    }

    const int dstw = dst_base + wid * DPW;
    const int2* tab_w = tab + (size_t)dstw * conn;
    const float* xr = x + (size_t)(token0 + wid) * src;   // warp's token row

    float st[8];                            // staged half-chunk (8 regs)

    // LDG half h (0/1) of chunk p into st[] (coalesced: lane consecutive)
#define LDG_HALF(p, h) do {                                                  \
        int _b = (p) * CHUNK + (h) * 256 + lane;                             \
        _Pragma("unroll")                                                    \
        for (int _i = 0; _i < 8; _i++) st[_i] = xr[_b + _i * 32];            \
    } while (0)

    // STS st[] as half h into buffer bb (stride-33 words: conflict-free)
#define STS_HALF(bb, h) do {                                                 \
        float* _d = xs + (bb) * BUFW + wid;                                  \
        _Pragma("unroll")                                                    \
        for (int _i = 0; _i < 8; _i++)                                       \
            _d[((h) * 256 + lane + _i * 32) * S] = st[_i];                   \
    } while (0)

    // gather dsts [d0,d1) from buf (int4 table pairs, 2 indep chains)
#define GATHER(d0, d1) do {                                                  \
        _Pragma("unroll")                                                    \
        for (int d = (d0); d < (d1); d++) {                                  \
            int e  = __shfl_sync(0xffffffffu, e_cur, d);                     \
            int e1 = __shfl_sync(0xffffffffu, e_nxt, d);                     \
            const int2* t = tab_w + d * conn;                                \
            float a0 = 0.f, a1 = 0.f;                                        \
            if ((e & 1) && e < e1) {                                         \
                int2 q = t[e++];                                             \
                a0 = fmaf(__int_as_float(q.y), buf[q.x], a0);                \
            }                                                                \
            for (; e + 1 < e1; e += 2) {                                     \
                int4 q = *(const int4*)&t[e];                                \
                a0 = fmaf(__int_as_float(q.y), buf[q.x], a0);                \
                a1 = fmaf(__int_as_float(q.w), buf[q.z], a1);                \
            }                                                                \
            if (e < e1) {                                                    \
                int2 q = t[e];                                               \
                a0 = fmaf(__int_as_float(q.y), buf[q.x], a0);                \
            }                                                                \
            acc[d] += a0 + a1;                                               \
        }                                                                    \
    } while (0)

    float acc[DPW];
#pragma unroll
    for (int d = 0; d < DPW; d++) acc[d] = 0.0f;

    // ---- prologue: stage chunk 0 into buffer 0 ----
    LDG_HALF(0, 0); STS_HALF(0, 0);
    LDG_HALF(0, 1); STS_HALF(0, 1);
    __syncthreads();

    int e_cur = 0;                          // lane (d&15): running segment start

    for (int p = 0; p < passes; p++) {
        int e_nxt = spl[(p + 1) * n_dst + dstw + (lane & 15)];
        const bool more = (p + 1 < passes);
        const int nb = (p + 1) & 1;         // buffer being filled
        const float* buf = xs + (p & 1) * BUFW + lane;

        if (more) LDG_HALF(p + 1, 0);       // latency hidden under gather
        GATHER(0, 8);
        if (more) { STS_HALF(nb, 0); LDG_HALF(p + 1, 1); }
        GATHER(8, 16);
        if (more) STS_HALF(nb, 1);

        e_cur = e_nxt;
        __syncthreads();                    // chunk p+1 ready; buf p released
    }

    // ---- transpose through SMEM (all conflict-free), coalesced store ----
#pragma unroll
    for (int d = 0; d < DPW; d++)
        xs[(wid * DPW + d) * S + lane] = acc[d];
    __syncthreads();

    const int total = NDST * TOKS;          // 16384
    for (int i = tid; i < total; i += 1024) {
        int t = i >> 9;                     // token within tile (0..31)
        int c = i & (NDST - 1);             // local dst (lane-consecutive)
        out[(size_t)(token0 + t) * 2048 + col_off + dst_base + c] = xs[c * S + t];
    }
#undef LDG_HALF
#undef STS_HALF
#undef GATHER
}

// ---------------------------------------------------------------------------
// Launch
// ---------------------------------------------------------------------------
extern "C" void kernel_launch(void* const* d_in, const int* in_sizes, int n_in,
                              void* d_out, int out_size)
{
    // Layout detection: dict order vs signature order (w/m swap harmless).
    const float *xa, *wa, *ma, *xb, *wb, *mb, *xc, *wc, *mc;
    if (in_sizes[1] == 1024 * 4096) {           // dict order
        xa = (const float*)d_in[0]; wa = (const float*)d_in[1]; ma = (const float*)d_in[2];
        xb = (const float*)d_in[3]; wb = (const float*)d_in[4]; mb = (const float*)d_in[5];
        xc = (const float*)d_in[6]; wc = (const float*)d_in[7]; mc = (const float*)d_in[8];
    } else {                                    // signature order
        xa = (const float*)d_in[0]; xb = (const float*)d_in[1]; xc = (const float*)d_in[2];
        wa = (const float*)d_in[3]; wb = (const float*)d_in[4]; wc = (const float*)d_in[5];
        ma = (const float*)d_in[6]; mb = (const float*)d_in[7]; mc = (const float*)d_in[8];
    }
    float* out = (float*)d_out;

    cudaFuncSetAttribute(tract_fused, cudaFuncAttributeMaxDynamicSharedMemorySize,
                         SMEM_BYTES);

    // ---- one merged prep launch: 2048 warp-rows, 8 warps per block ----
    prep_all<<<256, 256>>>(wa, ma, wb, mb, wc, mc);

    // ---- fused sparse gather for all three tracts ----
    tract_fused<<<1024, 1024, SMEM_BYTES>>>(xa, xb, xc, out);
}

// round 8
// speedup vs baseline: 1.4218x; 1.4218x over previous
#include <cuda_runtime.h>
#include <cstdint>

// ---------------------------------------------------------------------------
// TractBundle: out = concat( x_a @ (Wa*Ma)^T, x_b @ (Wb*Mb)^T, x_c @ (Wc*Mc)^T )
// Masks: 64/64/32-sparse per row -> compressed sparse-gather.
// R7: grouped-contiguous tables (per warp-group of 16 dsts, entries laid out
// (pass, dst)-major -> sequential table stream per warp-pass), float2 tokens,
// CHUNK=256 double buffer with register-quarter staging, one barrier/pass.
// ---------------------------------------------------------------------------

#define CHUNK 256                   // src elements staged per pass
#define S     66                    // smem row stride (EVEN: float2 alignment)
#define TOKS  64                    // tokens per block (2 per lane, float2)
#define NDST  512                   // dst columns per block
#define DPW   16                    // dsts per warp (= group size)
#define BUFW  (CHUNK * S)           // 16896 floats per buffer
#define SMEM_BYTES (2 * BUFW * 4)   // 135168
#define SPLS  257                   // gspl stride per group (16 passes * 16 + 1)

// Grouped tables: group g (16 dsts) owns entries [g*16*conn, (g+1)*16*conn),
// ordered by (pass, dst, arbitrary). Entry = ( (src%CHUNK)*S , bits(w*m) ).
// gspl[g*SPLS + p*16 + d] = group-relative start of (pass p, dst d) segment;
// sentinel at [passes*16] = 16*conn.
__device__ __align__(16) int2 g_tabA[64 * 16 * 64];
__device__ __align__(16) int2 g_tabB[32 * 16 * 64];
__device__ __align__(16) int2 g_tabC[32 * 16 * 32];
__device__ int g_splA[64 * SPLS];
__device__ int g_splB[32 * SPLS];
__device__ int g_splC[32 * SPLS];

// ---------------------------------------------------------------------------
// Prep: one block per group of 16 dst rows (128 groups total), 512 threads.
// warp r <-> row r of the group. count per (row, chunk) -> serial scan in
// (pass, dst)-major order -> scatter entries into the grouped stream.
// ---------------------------------------------------------------------------
__global__ __launch_bounds__(512)
void prep_grouped(const float* __restrict__ wa, const float* __restrict__ ma,
                  const float* __restrict__ wb, const float* __restrict__ mb,
                  const float* __restrict__ wc, const float* __restrict__ mc)
{
    __shared__ int scnt[16][16];    // [dst][pass] counts
    __shared__ int soff[16][16];    // [dst][pass] group-relative offsets

    const int tid  = threadIdx.x;
    const int lane = tid & 31;
    const int r    = tid >> 5;      // warp = row within group

    const float *W, *M; int2* tab; int* gspl;
    int src, conn, group;
    int gb = blockIdx.x;
    if (gb < 64)      { W = wa; M = ma; tab = g_tabA; gspl = g_splA;
                        src = 4096; conn = 64; group = gb; }
    else if (gb < 96) { W = wb; M = mb; tab = g_tabB; gspl = g_splB;
                        src = 4096; conn = 64; group = gb - 64; }
    else              { W = wc; M = mc; tab = g_tabC; gspl = g_splC;
                        src = 2048; conn = 32; group = gb - 96; }

    const int passes = src / CHUNK;
    const int row = group * 16 + r;
    const float* wr = W + (size_t)row * src;
    const float* mr = M + (size_t)row * src;

    // ---- sweep 1: count nnz per chunk ----
    for (int c = 0; c < passes; c++) {
        int cnt = 0;
#pragma unroll
        for (int i = 0; i < CHUNK / 32; i++)
            cnt += (mr[c * CHUNK + i * 32 + lane] != 0.0f);
#pragma unroll
        for (int o = 16; o; o >>= 1) cnt += __shfl_xor_sync(0xffffffffu, cnt, o);
        if (lane == 0) scnt[r][c] = cnt;
    }
    __syncthreads();

    // ---- scan in (pass, dst)-major order ----
    if (tid == 0) {
        int run = 0;
        for (int p = 0; p < passes; p++)
            for (int d = 0; d < 16; d++) { soff[d][p] = run; run += scnt[d][p]; }
    }
    __syncthreads();

    // ---- write gspl ----
    if (tid < passes * 16) {
        int p = tid >> 4, d = tid & 15;
        gspl[group * SPLS + p * 16 + d] = soff[d][p];
    }
    if (tid == 0) gspl[group * SPLS + passes * 16] = 16 * conn;

    // ---- sweep 2: scatter entries ----
    int2* tg = tab + (size_t)group * 16 * conn;
    for (int c = 0; c < passes; c++) {
        int base = soff[r][c];
        for (int i = 0; i < CHUNK / 32; i++) {
            int s = c * CHUNK + i * 32 + lane;
            float mv = mr[s];
            unsigned bits = __ballot_sync(0xffffffffu, mv != 0.0f);
            if (mv != 0.0f) {
                int pos = base + __popc(bits & ((1u << lane) - 1u));
                tg[pos] = make_int2((s & (CHUNK - 1)) * S, __float_as_int(wr[s] * mv));
            }
            base += __popc(bits);
        }
    }
}

// ---------------------------------------------------------------------------
// Fused gather kernel, 512 blocks x 1024 threads (32 warps).
//   [0,256)   tract A: tile = b>>1 (64-token tiles), dstblk = b&1
//   [256,384) tract B;  [384,512) tract C
// Warp w owns dsts [dstw, dstw+16) = group (per-tract index). Per pass the
// warp's table entries are one contiguous stream: sequential int4 loads.
// Staging: register quarters of chunk p+1 interleaved with 4-dst gathers.
// ---------------------------------------------------------------------------
__global__ __launch_bounds__(1024, 1)
void tract_fused(const float* __restrict__ xa,
                 const float* __restrict__ xb,
                 const float* __restrict__ xc,
                 float* __restrict__ out)
{
    extern __shared__ float xs[];
    const int tid  = threadIdx.x;
    const int lane = tid & 31;
    const int wid  = tid >> 5;
    const int l16  = lane & 15;

    // ---- block -> (tract, tile, dst block) dispatch ----
    const float* x; const int2* tab; const int* gspl;
    int src, conn, passes, col_off, token0, dst_base, group;
    int b = blockIdx.x;
    if (b < 256) {
        x = xa; tab = g_tabA; gspl = g_splA;
        src = 4096; conn = 64; passes = 16;
        col_off = 0; token0 = (b >> 1) * TOKS; dst_base = (b & 1) * NDST;
        group = (b & 1) * 32 + wid;
    } else if (b < 384) {
        x = xb; tab = g_tabB; gspl = g_splB;
        src = 4096; conn = 64; passes = 16;
        col_off = 1024; token0 = (b - 256) * TOKS; dst_base = 0;
        group = wid;
    } else {
        x = xc; tab = g_tabC; gspl = g_splC;
        src = 2048; conn = 32; passes = 8;
        col_off = 1536; token0 = (b - 384) * TOKS; dst_base = 0;
        group = wid;
    }

    const int2* tg    = tab + (size_t)group * 16 * conn;  // warp's stream
    const int* gspl_g = gspl + group * SPLS;
    // thread's token pair: {2*wid, 2*wid+1} for staging; gathers use lane pair
    const float* xr0 = x + (size_t)(token0 + 2 * wid) * src;
    const float* xr1 = xr0 + src;

    float2 st[2];                           // staged quarter (4 regs)

    // LDG quarter q (0..3) of chunk p
#define LDG_Q(p, q) do {                                                     \
        int _b = (p) * CHUNK + (q) * 64 + lane;                              \
        st[0] = make_float2(xr0[_b],      xr1[_b]);                          \
        st[1] = make_float2(xr0[_b + 32], xr1[_b + 32]);                     \
    } while (0)

    // STS quarter q into buffer bb (STS.64, conflict-free)
#define STS_Q(bb, q) do {                                                    \
        float* _d = xs + (bb) * BUFW + 2 * wid;                              \
        *(float2*)&_d[((q) * 64 + lane) * S]      = st[0];                   \
        *(float2*)&_d[((q) * 64 + lane + 32) * S] = st[1];                   \
    } while (0)

    // gather dsts [d0,d1): contiguous table stream, int4 pairs, 4 FMA chains
#define GATHER(d0, d1) do {                                                  \
        _Pragma("unroll")                                                    \
        for (int d = (d0); d < (d1); d++) {                                  \
            int e  = __shfl_sync(0xffffffffu, e0v, d);                       \
            int e1 = __shfl_sync(0xffffffffu, e1v, d);                       \
            float a0x = 0.f, a0y = 0.f, a1x = 0.f, a1y = 0.f;                \
            if ((e & 1) && e < e1) {                                         \
                int2 q = tg[e++];                                            \
                float2 xv = *(const float2*)(buf + q.x);                     \
                float w = __int_as_float(q.y);                               \
                a0x = fmaf(w, xv.x, a0x);                                    \
                a0y = fmaf(w, xv.y, a0y);                                    \
            }                                                                \
            for (; e + 1 < e1; e += 2) {                                     \
                int4 q = *(const int4*)&tg[e];                               \
                float2 xv0 = *(const float2*)(buf + q.x);                    \
                float2 xv1 = *(const float2*)(buf + q.z);                    \
                float w0 = __int_as_float(q.y);                              \
                float w1 = __int_as_float(q.w);                              \
                a0x = fmaf(w0, xv0.x, a0x);                                  \
                a0y = fmaf(w0, xv0.y, a0y);                                  \
                a1x = fmaf(w1, xv1.x, a1x);                                  \
                a1y = fmaf(w1, xv1.y, a1y);                                  \
            }                                                                \
            if (e < e1) {                                                    \
                int2 q = tg[e];                                              \
                float2 xv = *(const float2*)(buf + q.x);                     \
                float w = __int_as_float(q.y);                               \
                a0x = fmaf(w, xv.x, a0x);                                    \
                a0y = fmaf(w, xv.y, a0y);                                    \
            }                                                                \
            acc[d].x += a0x + a1x;                                           \
            acc[d].y += a0y + a1y;                                           \
        }                                                                    \
    } while (0)

    float2 acc[DPW];
#pragma unroll
    for (int d = 0; d < DPW; d++) acc[d] = make_float2(0.0f, 0.0f);

    // ---- prologue: stage chunk 0 into buffer 0 ----
    LDG_Q(0, 0); STS_Q(0, 0);
    LDG_Q(0, 1); STS_Q(0, 1);
    LDG_Q(0, 2); STS_Q(0, 2);
    LDG_Q(0, 3); STS_Q(0, 3);
    __syncthreads();

    for (int p = 0; p < passes; p++) {
        // segment boundaries for this pass (tiny coalesced loads, L2-hot)
        int e0v = gspl_g[p * 16 + l16];
        int e1v = gspl_g[p * 16 + l16 + 1];

        const bool more = (p + 1 < passes);
        const int nb = (p + 1) & 1;
        const float* buf = xs + (p & 1) * BUFW + 2 * lane;

        if (more) LDG_Q(p + 1, 0);
        GATHER(0, 4);
        if (more) { STS_Q(nb, 0); LDG_Q(p + 1, 1); }
        GATHER(4, 8);
        if (more) { STS_Q(nb, 1); LDG_Q(p + 1, 2); }
        GATHER(8, 12);
        if (more) { STS_Q(nb, 2); LDG_Q(p + 1, 3); }
        GATHER(12, 16);
        if (more) STS_Q(nb, 3);

        __syncthreads();                    // chunk p+1 ready; buf p released
    }

    // ---- transpose through SMEM (conflict-free STS.64), coalesced store ----
#pragma unroll
    for (int d = 0; d < DPW; d++)
        *(float2*)&xs[(wid * DPW + d) * S + 2 * lane] = acc[d];
    __syncthreads();

    const int total = NDST * TOKS;          // 32768
    for (int i = tid; i < total; i += 1024) {
        int t = i >> 9;                     // token within tile (0..63)
        int c = i & (NDST - 1);             // local dst
        out[(size_t)(token0 + t) * 2048 + col_off + dst_base + c] = xs[c * S + t];
    }
#undef LDG_Q
#undef STS_Q
#undef GATHER
}

// ---------------------------------------------------------------------------
// Launch
// ---------------------------------------------------------------------------
extern "C" void kernel_launch(void* const* d_in, const int* in_sizes, int n_in,
                              void* d_out, int out_size)
{
    // Layout detection: dict order vs signature order (w/m swap harmless).
    const float *xa, *wa, *ma, *xb, *wb, *mb, *xc, *wc, *mc;
    if (in_sizes[1] == 1024 * 4096) {           // dict order
        xa = (const float*)d_in[0]; wa = (const float*)d_in[1]; ma = (const float*)d_in[2];
        xb = (const float*)d_in[3]; wb = (const float*)d_in[4]; mb = (const float*)d_in[5];
        xc = (const float*)d_in[6]; wc = (const float*)d_in[7]; mc = (const float*)d_in[8];
    } else {                                    // signature order
        xa = (const float*)d_in[0]; xb = (const float*)d_in[1]; xc = (const float*)d_in[2];
        wa = (const float*)d_in[3]; wb = (const float*)d_in[4]; wc = (const float*)d_in[5];
        ma = (const float*)d_in[6]; mb = (const float*)d_in[7]; mc = (const float*)d_in[8];
    }
    float* out = (float*)d_out;

    cudaFuncSetAttribute(tract_fused, cudaFuncAttributeMaxDynamicSharedMemorySize,
                         SMEM_BYTES);

    // ---- prep: 128 groups (64 A + 32 B + 32 C), one block each ----
    prep_grouped<<<128, 512>>>(wa, ma, wb, mb, wc, mc);

    // ---- fused sparse gather for all three tracts ----
    tract_fused<<<512, 1024, SMEM_BYTES>>>(xa, xb, xc, out);
}